// round 13
// baseline (speedup 1.0000x reference)
#include <cuda_runtime.h>

#define EDIM 512
#define HDIM 256
#define QN   1024
#define SN   512
#define NSTEP 3
#define NBLK  148

// ---------------- scratch (no allocations allowed) ----------------
__device__ float g_tmp[(QN + SN) * HDIM];   // hidden of encoder MLP
__device__ float g_enc[(QN + SN) * HDIM];   // q rows [0,1024), s rows [1024,1536)
__device__ float g_A[SN * HDIM];
__device__ float g_Bm[SN * HDIM];
__device__ float g_Hagg[SN * HDIM];
__device__ float g_hq[QN * HDIM];
__device__ float g_hs[SN * HDIM];
__device__ float g_rdenom[SN];
__device__ float g_flag[SN];
__device__ unsigned g_bar_cnt = 0;
__device__ unsigned g_bar_gen = 0;

struct Smem {
    float As[2][2][16][32];   // [half][buf][k][m]
    float Bs[2][2][16][64];   // [half][buf][k][n]
    float ws[2][2][16];
    float red[2048];
    int   ys[SN];
    short list2[2][SN];
    int   scnt[2];
};

__device__ __forceinline__ void half_bar(int half) {
    // decoupled 256-thread barrier per K-half (tids 0-255 / 256-511)
    asm volatile("bar.sync %0, %1;" :: "r"(half + 1), "r"(256) : "memory");
}

// grid-wide barrier: all NBLK CTAs resident (grid <= SM count), sense-reversing.
// __threadfence() at gpu scope emits CCTL.IVALL on sm_103a -> L1D invalidated,
// so post-barrier plain loads observe other SMs' writes via L2.
__device__ __forceinline__ void grid_bar() {
    __syncthreads();
    if (threadIdx.x == 0) {
        __threadfence();                       // release (cumulative w/ bar above)
        unsigned gen = *(volatile unsigned*)&g_bar_gen;
        unsigned a = atomicAdd(&g_bar_cnt, 1u);
        if (a == (unsigned)(gridDim.x - 1)) {
            *(volatile unsigned*)&g_bar_cnt = 0u;
            __threadfence();
            *(volatile unsigned*)&g_bar_gen = gen + 1u;
        } else {
            while (*(volatile unsigned*)&g_bar_gen == gen) { __nanosleep(64); }
        }
        __threadfence();                       // acquire + L1D invalidate
    }
    __syncthreads();
}

// ---------------- one 32x64 GEMM tile: C = A(MxK) @ B(KxN=256) ----------------
// 512 threads, intra-block split-K (2 halves), double-buffered, 2x4 micro-tile.
template <int RELU, int ACCUM, int ROWFLAG>
__device__ __forceinline__ void gemm_tile(
    Smem& sm, const float* __restrict__ A, const float* __restrict__ B,
    float* __restrict__ C, const float* __restrict__ bias,
    int K, int m0, int n0)
{
    const int tid  = threadIdx.x;
    const int half = tid >> 8;
    const int t    = tid & 255;
    const int tx = t & 15, ty = t >> 4;
    const int lr = t & 31, lc4 = (t >> 5) & 3;     // A-tile load (t<128)
    const int bk = t >> 4, bn4 = t & 15;           // B-tile load (all 256)

    const int K2     = K >> 1;
    const int kbase  = half * K2;
    const int ntiles = K2 >> 4;

    // prologue: tile 0 -> buf 0
    {
        float4 av = make_float4(0.f, 0.f, 0.f, 0.f);
        if (t < 128) av = *(const float4*)(A + (m0 + lr) * K + kbase + 4 * lc4);
        float4 bv = *(const float4*)(B + (kbase + bk) * HDIM + n0 + 4 * bn4);
        if (t < 128) {
            sm.As[half][0][4 * lc4 + 0][lr] = av.x;
            sm.As[half][0][4 * lc4 + 1][lr] = av.y;
            sm.As[half][0][4 * lc4 + 2][lr] = av.z;
            sm.As[half][0][4 * lc4 + 3][lr] = av.w;
        }
        *(float4*)&sm.Bs[half][0][bk][4 * bn4] = bv;
        half_bar(half);
    }

    float acc[2][4] = {};

    for (int it = 0; it < ntiles; it++) {
        const int buf = it & 1;
        float4 av2 = make_float4(0.f, 0.f, 0.f, 0.f);
        float4 bv2 = make_float4(0.f, 0.f, 0.f, 0.f);
        const bool more = (it + 1 < ntiles);
        if (more) {
            const int k0 = kbase + (it + 1) * 16;
            if (t < 128) av2 = *(const float4*)(A + (m0 + lr) * K + k0 + 4 * lc4);
            bv2 = *(const float4*)(B + (k0 + bk) * HDIM + n0 + 4 * bn4);
        }

#pragma unroll
        for (int kk = 0; kk < 16; kk++) {
            float2 a2 = *(const float2*)&sm.As[half][buf][kk][ty * 2];
            float4 b4 = *(const float4*)&sm.Bs[half][buf][kk][tx * 4];
            float a[2] = {a2.x, a2.y};
            float b[4] = {b4.x, b4.y, b4.z, b4.w};
#pragma unroll
            for (int r = 0; r < 2; r++)
#pragma unroll
                for (int c = 0; c < 4; c++) acc[r][c] += a[r] * b[c];
        }

        if (more) {
            const int nb = buf ^ 1;
            if (t < 128) {
                sm.As[half][nb][4 * lc4 + 0][lr] = av2.x;
                sm.As[half][nb][4 * lc4 + 1][lr] = av2.y;
                sm.As[half][nb][4 * lc4 + 2][lr] = av2.z;
                sm.As[half][nb][4 * lc4 + 3][lr] = av2.w;
            }
            *(float4*)&sm.Bs[half][nb][bk][4 * bn4] = bv2;
            half_bar(half);
        }
    }

    // deterministic cross-half reduction: half1 stores, half0 adds + epilogue
    __syncthreads();
    if (half == 1) {
        *(float4*)&sm.red[t * 8 + 0] = make_float4(acc[0][0], acc[0][1], acc[0][2], acc[0][3]);
        *(float4*)&sm.red[t * 8 + 4] = make_float4(acc[1][0], acc[1][1], acc[1][2], acc[1][3]);
    }
    __syncthreads();
    if (half == 0) {
        float4 r0 = *(const float4*)&sm.red[t * 8 + 0];
        float4 r1 = *(const float4*)&sm.red[t * 8 + 4];
        acc[0][0] += r0.x; acc[0][1] += r0.y; acc[0][2] += r0.z; acc[0][3] += r0.w;
        acc[1][0] += r1.x; acc[1][1] += r1.y; acc[1][2] += r1.z; acc[1][3] += r1.w;

        const int m = m0 + ty * 2;
        const int n = n0 + tx * 4;
        float bb[4] = {0.f, 0.f, 0.f, 0.f};
        if (bias) {
            bb[0] = bias[n]; bb[1] = bias[n + 1]; bb[2] = bias[n + 2]; bb[3] = bias[n + 3];
        }
#pragma unroll
        for (int r = 0; r < 2; r++) {
            const float fl = ROWFLAG ? g_flag[m + r] : 1.0f;
            float v[4];
#pragma unroll
            for (int c = 0; c < 4; c++) v[c] = acc[r][c] + bb[c] * fl;
            if (ACCUM) {
                float4 cv = *(const float4*)(C + (m + r) * HDIM + n);
                v[0] += cv.x; v[1] += cv.y; v[2] += cv.z; v[3] += cv.w;
            }
            if (RELU) {
#pragma unroll
                for (int c = 0; c < 4; c++) v[c] = fmaxf(v[c], 0.f);
            }
            *(float4*)(C + (m + r) * HDIM + n) = make_float4(v[0], v[1], v[2], v[3]);
        }
    }
    __syncthreads();
}

// ---------------- masked relu-sum aggregation (two rows per CTA pass) --------
__device__ __forceinline__ void hagg_task(Smem& sm, const float* __restrict__ bm1t,
                                          int task)
{
    const int tid   = threadIdx.x;
    const int group = tid >> 8;
    const int t     = tid & 255;
    const int i     = task * 2 + group;

    const int yi = sm.ys[i];
    if (t < 32) {                  // group's first warp builds an ascending list
        int cnt = 0;
        for (int it = 0; it < SN / 32; it++) {
            int j = it * 32 + t;
            bool m = (sm.ys[j] == yi) && (j != i);
            unsigned mask = __ballot_sync(0xffffffffu, m);
            if (m) {
                int pos = cnt + __popc(mask & ((1u << t) - 1u));
                sm.list2[group][pos] = (short)j;
            }
            cnt += __popc(mask);
        }
        if (t == 0) sm.scnt[group] = cnt;
    }
    half_bar(group);

    const int cnt = sm.scnt[group];
    const float ai = g_A[i * HDIM + t] + bm1t[t];
    float acc = 0.f;
    int l = 0;
    for (; l + 4 <= cnt; l += 4) {           // MLP=4 against L2 latency
        int j0 = sm.list2[group][l],     j1 = sm.list2[group][l + 1];
        int j2 = sm.list2[group][l + 2], j3 = sm.list2[group][l + 3];
        float v0 = g_Bm[j0 * HDIM + t];
        float v1 = g_Bm[j1 * HDIM + t];
        float v2 = g_Bm[j2 * HDIM + t];
        float v3 = g_Bm[j3 * HDIM + t];
        acc += fmaxf(ai + v0, 0.f);
        acc += fmaxf(ai + v1, 0.f);
        acc += fmaxf(ai + v2, 0.f);
        acc += fmaxf(ai + v3, 0.f);
    }
    for (; l < cnt; l++) {
        int j = sm.list2[group][l];
        acc += fmaxf(ai + g_Bm[j * HDIM + t], 0.f);
    }
    g_Hagg[i * HDIM + t] = acc * g_rdenom[i];
    half_bar(group);               // protect list reuse on next task
}

// ---------------- one 32x64 scores tile --------------------------------------
// scores[i][j] = sum_h relu(hq[i][h] + hs[j][h]) * wr2[h] + br2
__device__ __forceinline__ void scores_tile(Smem& sm, const float* __restrict__ wr2,
                                            float br2, float* __restrict__ out,
                                            int m0, int n0)
{
    const int tid  = threadIdx.x;
    const int half = tid >> 8;
    const int t    = tid & 255;
    const int tx = t & 15, ty = t >> 4;
    const int lr = t & 31, lc4 = (t >> 5) & 3;   // hq load (t<128)
    const int jr = t & 63, jc4 = t >> 6;         // hs load (all 256)

    const int kbase  = half * (HDIM / 2);
    const int ntiles = (HDIM / 2) >> 4;

    // prologue
    {
        float4 av = make_float4(0.f, 0.f, 0.f, 0.f);
        if (t < 128) av = *(const float4*)(g_hq + (m0 + lr) * HDIM + kbase + 4 * lc4);
        float4 bv = *(const float4*)(g_hs + (n0 + jr) * HDIM + kbase + 4 * jc4);
        if (t < 128) {
            sm.As[half][0][4 * lc4 + 0][lr] = av.x;
            sm.As[half][0][4 * lc4 + 1][lr] = av.y;
            sm.As[half][0][4 * lc4 + 2][lr] = av.z;
            sm.As[half][0][4 * lc4 + 3][lr] = av.w;
        }
        sm.Bs[half][0][4 * jc4 + 0][jr] = bv.x;
        sm.Bs[half][0][4 * jc4 + 1][jr] = bv.y;
        sm.Bs[half][0][4 * jc4 + 2][jr] = bv.z;
        sm.Bs[half][0][4 * jc4 + 3][jr] = bv.w;
        if (t < 16) sm.ws[half][0][t] = wr2[kbase + t];
        half_bar(half);
    }

    float acc[2][4] = {};

    for (int it = 0; it < ntiles; it++) {
        const int buf = it & 1;
        float4 av2 = make_float4(0.f, 0.f, 0.f, 0.f);
        float4 bv2 = make_float4(0.f, 0.f, 0.f, 0.f);
        float wv2 = 0.f;
        const bool more = (it + 1 < ntiles);
        if (more) {
            const int k0 = kbase + (it + 1) * 16;
            if (t < 128) av2 = *(const float4*)(g_hq + (m0 + lr) * HDIM + k0 + 4 * lc4);
            bv2 = *(const float4*)(g_hs + (n0 + jr) * HDIM + k0 + 4 * jc4);
            if (t < 16) wv2 = wr2[k0 + t];
        }

#pragma unroll
        for (int kk = 0; kk < 16; kk++) {
            const float w = sm.ws[half][buf][kk];
            float2 a2 = *(const float2*)&sm.As[half][buf][kk][ty * 2];
            float4 b4 = *(const float4*)&sm.Bs[half][buf][kk][tx * 4];
            float a[2] = {a2.x, a2.y};
            float b[4] = {b4.x, b4.y, b4.z, b4.w};
#pragma unroll
            for (int r = 0; r < 2; r++)
#pragma unroll
                for (int c = 0; c < 4; c++)
                    acc[r][c] += fmaxf(a[r] + b[c], 0.f) * w;
        }

        if (more) {
            const int nb = buf ^ 1;
            if (t < 128) {
                sm.As[half][nb][4 * lc4 + 0][lr] = av2.x;
                sm.As[half][nb][4 * lc4 + 1][lr] = av2.y;
                sm.As[half][nb][4 * lc4 + 2][lr] = av2.z;
                sm.As[half][nb][4 * lc4 + 3][lr] = av2.w;
            }
            sm.Bs[half][nb][4 * jc4 + 0][jr] = bv2.x;
            sm.Bs[half][nb][4 * jc4 + 1][jr] = bv2.y;
            sm.Bs[half][nb][4 * jc4 + 2][jr] = bv2.z;
            sm.Bs[half][nb][4 * jc4 + 3][jr] = bv2.w;
            if (t < 16) sm.ws[half][nb][t] = wv2;
            half_bar(half);
        }
    }

    __syncthreads();
    if (half == 1) {
        *(float4*)&sm.red[t * 8 + 0] = make_float4(acc[0][0], acc[0][1], acc[0][2], acc[0][3]);
        *(float4*)&sm.red[t * 8 + 4] = make_float4(acc[1][0], acc[1][1], acc[1][2], acc[1][3]);
    }
    __syncthreads();
    if (half == 0) {
        float4 r0 = *(const float4*)&sm.red[t * 8 + 0];
        float4 r1 = *(const float4*)&sm.red[t * 8 + 4];
        acc[0][0] += r0.x; acc[0][1] += r0.y; acc[0][2] += r0.z; acc[0][3] += r0.w;
        acc[1][0] += r1.x; acc[1][1] += r1.y; acc[1][2] += r1.z; acc[1][3] += r1.w;

        const int m = m0 + ty * 2;
        const int n = n0 + tx * 4;
#pragma unroll
        for (int r = 0; r < 2; r++) {
            *(float4*)(out + (m + r) * SN + n) =
                make_float4(acc[r][0] + br2, acc[r][1] + br2, acc[r][2] + br2, acc[r][3] + br2);
        }
    }
    __syncthreads();
}

// ---------------- the whole network in one persistent kernel -----------------
__global__ __launch_bounds__(512, 1) void fused_k(
    const float* __restrict__ qf,  const float* __restrict__ sf,
    const int*   __restrict__ y,
    const float* __restrict__ Wn1, const float* __restrict__ bn1,
    const float* __restrict__ Wn2, const float* __restrict__ bn2,
    const float* __restrict__ Wm1, const float* __restrict__ bm1,
    const float* __restrict__ Wm2, const float* __restrict__ bm2,
    const float* __restrict__ Wr1, const float* __restrict__ br1,
    const float* __restrict__ wr2, const float* __restrict__ br2,
    float* __restrict__ out)
{
    __shared__ Smem sm;
    const int tid = threadIdx.x;
    const int bid = blockIdx.x;

    sm.ys[tid] = y[tid];                 // 512 threads == SN
    __syncthreads();

    float* senc = g_enc + QN * HDIM;

    // P0: class counts (CTA 0) + encoder layer 1 (192 tiles)
    if (bid == 0) {
        int yi = sm.ys[tid];
        int c = -1;
        for (int j = 0; j < SN; j++) c += (sm.ys[j] == yi);
        g_rdenom[tid] = 1.0f / fmaxf((float)c, 1.0f);
        g_flag[tid]   = (c > 0) ? 1.0f : 0.0f;
    }
    for (int id = bid; id < 192; id += NBLK) {
        if (id < 128)
            gemm_tile<1, 0, 0>(sm, qf, Wn1, g_tmp, bn1, EDIM, (id >> 2) * 32, (id & 3) * 64);
        else {
            int l = id - 128;
            gemm_tile<1, 0, 0>(sm, sf, Wn1, g_tmp + QN * HDIM, bn1, EDIM,
                               (l >> 2) * 32, (l & 3) * 64);
        }
    }
    grid_bar();

    // P1: encoder layer 2 (192 tiles, M=1536)
    for (int id = bid; id < 192; id += NBLK)
        gemm_tile<0, 0, 0>(sm, g_tmp, Wn2, g_enc, bn2, HDIM, (id >> 2) * 32, (id & 3) * 64);
    grid_bar();

    // message-passing steps
    for (int st = 0; st < NSTEP; st++) {
        const float* Wm1t = Wm1 + (size_t)st * 2 * HDIM * HDIM;
        const float* Wm2t = Wm2 + (size_t)st * HDIM * HDIM;
        const float* bm1t = bm1 + (size_t)st * HDIM;
        const float* bm2t = bm2 + (size_t)st * HDIM;

        // A = s@W1a (64), B = s@W1b (64); step 0 also computes hq = q@Wr1a+br1 (128)
        const int ntA = (st == 0) ? 256 : 128;
        for (int id = bid; id < ntA; id += NBLK) {
            if (id < 64)
                gemm_tile<0, 0, 0>(sm, senc, Wm1t, g_A, nullptr, HDIM,
                                   (id >> 2) * 32, (id & 3) * 64);
            else if (id < 128) {
                int l = id - 64;
                gemm_tile<0, 0, 0>(sm, senc, Wm1t + HDIM * HDIM, g_Bm, nullptr, HDIM,
                                   (l >> 2) * 32, (l & 3) * 64);
            } else {
                int l = id - 128;
                gemm_tile<0, 0, 0>(sm, g_enc, Wr1, g_hq, br1, HDIM,
                                   (l >> 2) * 32, (l & 3) * 64);
            }
        }
        grid_bar();

        // masked relu aggregation (256 tasks x 2 rows)
        for (int task = bid; task < SN / 2; task += NBLK)
            hagg_task(sm, bm1t, task);
        grid_bar();

        // s += Hagg @ Wm2t + flag_i * bm2t   (64 tiles)
        for (int id = bid; id < 64; id += NBLK)
            gemm_tile<0, 1, 1>(sm, g_Hagg, Wm2t, senc, bm2t, HDIM,
                               (id >> 2) * 32, (id & 3) * 64);
        grid_bar();
    }

    // hs = s @ Wr1b   (64 tiles)
    for (int id = bid; id < 64; id += NBLK)
        gemm_tile<0, 0, 0>(sm, senc, Wr1 + HDIM * HDIM, g_hs, nullptr, HDIM,
                           (id >> 2) * 32, (id & 3) * 64);
    grid_bar();

    // scores (256 tiles of 32x64)
    const float br2v = br2[0];
    for (int id = bid; id < 256; id += NBLK)
        scores_tile(sm, wr2, br2v, out, (id >> 3) * 32, (id & 7) * 64);
}

// ---------------- host launcher ----------------
extern "C" void kernel_launch(void* const* d_in, const int* in_sizes, int n_in,
                              void* d_out, int out_size) {
    (void)in_sizes; (void)n_in; (void)out_size;
    const float* qf  = (const float*)d_in[0];
    const float* sf  = (const float*)d_in[1];
    const int*   y   = (const int*)  d_in[2];
    const float* Wn1 = (const float*)d_in[3];
    const float* bn1 = (const float*)d_in[4];
    const float* Wn2 = (const float*)d_in[5];
    const float* bn2 = (const float*)d_in[6];
    const float* Wm1 = (const float*)d_in[7];
    const float* bm1 = (const float*)d_in[8];
    const float* Wm2 = (const float*)d_in[9];
    const float* bm2 = (const float*)d_in[10];
    const float* Wr1 = (const float*)d_in[11];
    const float* br1 = (const float*)d_in[12];
    const float* wr2 = (const float*)d_in[13];
    const float* br2 = (const float*)d_in[14];
    float* out = (float*)d_out;

    fused_k<<<NBLK, 512>>>(qf, sf, y, Wn1, bn1, Wn2, bn2,
                           Wm1, bm1, Wm2, bm2, Wr1, br1, wr2, br2, out);
}